// round 1
// baseline (speedup 1.0000x reference)
#include <cuda_runtime.h>
#include <math.h>

// Problem constants
#define BB  2
#define LL  1024
#define DD  1024
#define HH  16
#define HD  64
#define NLAYER 8
#define FF  4096
#define TT  2048          // B*L
#define D3  3072          // 3*D

// ---------------- scratch (static device globals; no allocation) ----------------
__device__ float g_x   [TT * DD];                      // residual stream
__device__ float g_qkv [TT * D3];                      // qkv projection
__device__ float g_att [(size_t)32 * 1024 * 1024];     // attention scores/probs (bh, q, k)
__device__ float g_o   [TT * DD];                      // attn output (pre-proj)
__device__ float g_h   [TT * FF];                      // ffn hidden
__device__ float g_y   [TT * DD];                      // delta buffer (attn proj / ffn out)

// ---------------- embedding + input proj + posenc ----------------
__global__ void embed_kernel(const int* __restrict__ card_ids,
                             const int* __restrict__ action_ids,
                             const float* __restrict__ bet,
                             const float* __restrict__ card_tab,
                             const float* __restrict__ action_tab,
                             const float* __restrict__ bet_W,
                             const float* __restrict__ bet_b,
                             const float* __restrict__ in_W,
                             const float* __restrict__ in_b)
{
    int t = blockIdx.x;          // token index 0..2047
    int l = t & (LL - 1);        // position within sequence
    __shared__ float tok[48];
    int tid = threadIdx.x;
    if (tid < 16)       tok[tid] = card_tab[card_ids[t] * 16 + tid];
    else if (tid < 32)  tok[tid] = action_tab[action_ids[t] * 16 + (tid - 16)];
    else if (tid < 48)  tok[tid] = bet[t] * bet_W[tid - 32] + bet_b[tid - 32];
    __syncthreads();

    const float cdiv = -9.210340371976184f / 1024.0f;   // -ln(10000)/D
    for (int d = tid; d < DD; d += 256) {
        float acc = in_b[d];
        #pragma unroll
        for (int c = 0; c < 48; c++) acc += tok[c] * in_W[c * DD + d];
        int j2 = d & ~1;                                  // 2*(d/2)
        float ang = (float)l * expf((float)j2 * cdiv);
        float pe = (d & 1) ? cosf(ang) : sinf(ang);
        g_x[t * DD + d] = acc + pe;
    }
}

// ---------------- fp32 SGEMM: C[M,N] = A[M,K] @ W[K,N] + bias, optional relu ----------------
// BM=BN=64, BK=16, 256 threads, 4x4 per thread. M,N multiples of 64, K multiple of 16.
__global__ __launch_bounds__(256) void sgemm_kernel(const float* __restrict__ A,
                                                    const float* __restrict__ W,
                                                    const float* __restrict__ bias,
                                                    float* __restrict__ C,
                                                    int M, int N, int K, int relu)
{
    __shared__ float As[64][16];
    __shared__ float Ws[16][64];
    int tid = threadIdx.x;
    int tx = tid & 15, ty = tid >> 4;
    int rowBase = blockIdx.y * 64;
    int colBase = blockIdx.x * 64;

    float acc[4][4] = {};

    int amr = tid >> 4;      // 0..15 (A row sub-index)
    int akk = tid & 15;      // 0..15 (A k index)
    int wkk = tid >> 6;      // 0..3  (W k sub-index)
    int wn  = tid & 63;      // 0..63 (W col index)

    for (int k0 = 0; k0 < K; k0 += 16) {
        #pragma unroll
        for (int r = 0; r < 4; r++)
            As[amr + r * 16][akk] = A[(size_t)(rowBase + amr + r * 16) * K + k0 + akk];
        #pragma unroll
        for (int r = 0; r < 4; r++)
            Ws[wkk + r * 4][wn] = W[(size_t)(k0 + wkk + r * 4) * N + colBase + wn];
        __syncthreads();

        #pragma unroll
        for (int kk = 0; kk < 16; kk++) {
            float a0 = As[ty * 4 + 0][kk];
            float a1 = As[ty * 4 + 1][kk];
            float a2 = As[ty * 4 + 2][kk];
            float a3 = As[ty * 4 + 3][kk];
            float4 bv = *(const float4*)&Ws[kk][tx * 4];
            acc[0][0] += a0 * bv.x; acc[0][1] += a0 * bv.y; acc[0][2] += a0 * bv.z; acc[0][3] += a0 * bv.w;
            acc[1][0] += a1 * bv.x; acc[1][1] += a1 * bv.y; acc[1][2] += a1 * bv.z; acc[1][3] += a1 * bv.w;
            acc[2][0] += a2 * bv.x; acc[2][1] += a2 * bv.y; acc[2][2] += a2 * bv.z; acc[2][3] += a2 * bv.w;
            acc[3][0] += a3 * bv.x; acc[3][1] += a3 * bv.y; acc[3][2] += a3 * bv.z; acc[3][3] += a3 * bv.w;
        }
        __syncthreads();
    }

    #pragma unroll
    for (int i = 0; i < 4; i++) {
        int m = rowBase + ty * 4 + i;
        int n0 = colBase + tx * 4;
        float4 o;
        o.x = acc[i][0] + bias[n0 + 0];
        o.y = acc[i][1] + bias[n0 + 1];
        o.z = acc[i][2] + bias[n0 + 2];
        o.w = acc[i][3] + bias[n0 + 3];
        if (relu) {
            o.x = fmaxf(o.x, 0.f); o.y = fmaxf(o.y, 0.f);
            o.z = fmaxf(o.z, 0.f); o.w = fmaxf(o.w, 0.f);
        }
        *(float4*)&C[(size_t)m * N + n0] = o;
    }
}

// ---------------- attention scores: S = Q K^T / 8 with causal mask ----------------
// grid: (kt=16, qt=16, bh=32); block 256. Computes only kt<=qt tiles.
__global__ __launch_bounds__(256) void scores_kernel()
{
    int kt = blockIdx.x, qt = blockIdx.y, bh = blockIdx.z;
    if (kt > qt) return;
    int b = bh >> 4, h = bh & 15;
    __shared__ float Qs[64][65];
    __shared__ float Ks[64][65];
    int tid = threadIdx.x;

    for (int i = tid; i < 4096; i += 256) {
        int r = i >> 6, dd = i & 63;
        Qs[dd][r] = g_qkv[(size_t)(b * LL + qt * 64 + r) * D3 + h * 64 + dd];
        Ks[dd][r] = g_qkv[(size_t)(b * LL + kt * 64 + r) * D3 + DD + h * 64 + dd];
    }
    __syncthreads();

    int tx = tid & 15, ty = tid >> 4;
    float acc[4][4] = {};
    #pragma unroll 8
    for (int dd = 0; dd < 64; dd++) {
        float a[4], bv[4];
        #pragma unroll
        for (int i = 0; i < 4; i++) a[i] = Qs[dd][ty * 4 + i];
        #pragma unroll
        for (int j = 0; j < 4; j++) bv[j] = Ks[dd][tx * 4 + j];
        #pragma unroll
        for (int i = 0; i < 4; i++)
            #pragma unroll
            for (int j = 0; j < 4; j++)
                acc[i][j] += a[i] * bv[j];
    }

    #pragma unroll
    for (int i = 0; i < 4; i++) {
        int q = qt * 64 + ty * 4 + i;
        #pragma unroll
        for (int j = 0; j < 4; j++) {
            int k = kt * 64 + tx * 4 + j;
            g_att[((size_t)bh * LL + q) * LL + k] = (k <= q) ? acc[i][j] * 0.125f : -1e30f;
        }
    }
}

// ---------------- row softmax over k in [0, roundup(q+1,64)) ----------------
__global__ __launch_bounds__(256) void softmax_kernel()
{
    int q = blockIdx.x, bh = blockIdx.y;
    int n = ((q >> 6) + 1) << 6;
    float* row = g_att + ((size_t)bh * LL + q) * LL;
    int tid = threadIdx.x, lane = tid & 31, warp = tid >> 5;
    __shared__ float redm[8];
    __shared__ float reds[8];

    float v[4];
    float mx = -1e30f;
    #pragma unroll
    for (int r = 0; r < 4; r++) {
        int k = tid + r * 256;
        v[r] = (k < n) ? row[k] : -1e30f;
        mx = fmaxf(mx, v[r]);
    }
    #pragma unroll
    for (int o = 16; o > 0; o >>= 1) mx = fmaxf(mx, __shfl_xor_sync(0xffffffffu, mx, o));
    if (lane == 0) redm[warp] = mx;
    __syncthreads();
    if (tid == 0) {
        float m = redm[0];
        #pragma unroll
        for (int i = 1; i < 8; i++) m = fmaxf(m, redm[i]);
        redm[0] = m;
    }
    __syncthreads();
    mx = redm[0];

    float s = 0.f;
    #pragma unroll
    for (int r = 0; r < 4; r++) {
        int k = tid + r * 256;
        if (k < n) { v[r] = expf(v[r] - mx); s += v[r]; }
        else v[r] = 0.f;
    }
    #pragma unroll
    for (int o = 16; o > 0; o >>= 1) s += __shfl_xor_sync(0xffffffffu, s, o);
    if (lane == 0) reds[warp] = s;
    __syncthreads();
    if (tid == 0) {
        float t = 0.f;
        #pragma unroll
        for (int i = 0; i < 8; i++) t += reds[i];
        reds[0] = t;
    }
    __syncthreads();
    float inv = 1.f / reds[0];

    #pragma unroll
    for (int r = 0; r < 4; r++) {
        int k = tid + r * 256;
        if (k < n) row[k] = v[r] * inv;
    }
}

// ---------------- O = attn @ V  (per b,h; 64-query tiles; loops kt<=qt) ----------------
__global__ __launch_bounds__(256) void attnv_kernel()
{
    int qt = blockIdx.x, bh = blockIdx.y;
    int b = bh >> 4, h = bh & 15;
    __shared__ float At[64][65];
    __shared__ float Vs[64][64];
    int tid = threadIdx.x, tx = tid & 15, ty = tid >> 4;
    float acc[4][4] = {};

    for (int kt = 0; kt <= qt; kt++) {
        for (int i = tid; i < 4096; i += 256) {
            int r = i >> 6, c = i & 63;
            At[c][r] = g_att[((size_t)bh * LL + qt * 64 + r) * LL + kt * 64 + c];
            Vs[r][c] = g_qkv[(size_t)(b * LL + kt * 64 + r) * D3 + 2 * DD + h * 64 + c];
        }
        __syncthreads();
        #pragma unroll 8
        for (int kk = 0; kk < 64; kk++) {
            float a[4];
            #pragma unroll
            for (int i = 0; i < 4; i++) a[i] = At[kk][ty * 4 + i];
            float4 bv = *(const float4*)&Vs[kk][tx * 4];
            acc[0][0] += a[0] * bv.x; acc[0][1] += a[0] * bv.y; acc[0][2] += a[0] * bv.z; acc[0][3] += a[0] * bv.w;
            acc[1][0] += a[1] * bv.x; acc[1][1] += a[1] * bv.y; acc[1][2] += a[1] * bv.z; acc[1][3] += a[1] * bv.w;
            acc[2][0] += a[2] * bv.x; acc[2][1] += a[2] * bv.y; acc[2][2] += a[2] * bv.z; acc[2][3] += a[2] * bv.w;
            acc[3][0] += a[3] * bv.x; acc[3][1] += a[3] * bv.y; acc[3][2] += a[3] * bv.z; acc[3][3] += a[3] * bv.w;
        }
        __syncthreads();
    }

    #pragma unroll
    for (int i = 0; i < 4; i++) {
        int q = qt * 64 + ty * 4 + i;
        #pragma unroll
        for (int j = 0; j < 4; j++)
            g_o[(size_t)(b * LL + q) * DD + h * 64 + tx * 4 + j] = acc[i][j];
    }
}

// ---------------- residual add + layernorm ----------------
__global__ __launch_bounds__(256) void ln_kernel(const float* __restrict__ xin,
                                                 const float* __restrict__ delta,
                                                 const float* __restrict__ gamma,
                                                 const float* __restrict__ beta,
                                                 float* __restrict__ out)
{
    int row = blockIdx.x, tid = threadIdx.x, lane = tid & 31, warp = tid >> 5;
    __shared__ float red1[8];
    __shared__ float red2[8];
    __shared__ float stats[2];

    float v[4];
    float s = 0.f, s2 = 0.f;
    #pragma unroll
    for (int r = 0; r < 4; r++) {
        int d = tid + r * 256;
        float x = xin[(size_t)row * DD + d] + delta[(size_t)row * DD + d];
        v[r] = x; s += x; s2 += x * x;
    }
    #pragma unroll
    for (int o = 16; o > 0; o >>= 1) {
        s  += __shfl_xor_sync(0xffffffffu, s, o);
        s2 += __shfl_xor_sync(0xffffffffu, s2, o);
    }
    if (lane == 0) { red1[warp] = s; red2[warp] = s2; }
    __syncthreads();
    if (tid == 0) {
        float a = 0.f, c = 0.f;
        #pragma unroll
        for (int i = 0; i < 8; i++) { a += red1[i]; c += red2[i]; }
        float mu = a * (1.0f / DD);
        float var = c * (1.0f / DD) - mu * mu;
        stats[0] = mu;
        stats[1] = rsqrtf(var + 1e-5f);
    }
    __syncthreads();
    float mu = stats[0], rstd = stats[1];
    #pragma unroll
    for (int r = 0; r < 4; r++) {
        int d = tid + r * 256;
        out[(size_t)row * DD + d] = (v[r] - mu) * rstd * gamma[d] + beta[d];
    }
}

// ---------------- extract x[:, -1] ----------------
__global__ void final_kernel(float* __restrict__ out)
{
    int b = blockIdx.x;
    int d = blockIdx.y * 256 + threadIdx.x;
    out[b * DD + d] = g_x[(size_t)(b * LL + (LL - 1)) * DD + d];
}

// ---------------- host launch ----------------
extern "C" void kernel_launch(void* const* d_in, const int* in_sizes, int n_in,
                              void* d_out, int out_size)
{
    const int*   card_ids   = (const int*)  d_in[0];
    const int*   action_ids = (const int*)  d_in[1];
    const float* bet        = (const float*)d_in[2];
    const float* card_tab   = (const float*)d_in[3];
    const float* action_tab = (const float*)d_in[4];
    const float* bet_W      = (const float*)d_in[5];
    const float* bet_b      = (const float*)d_in[6];
    const float* in_W       = (const float*)d_in[7];
    const float* in_b       = (const float*)d_in[8];
    const float* qkv_W      = (const float*)d_in[9];
    const float* qkv_b      = (const float*)d_in[10];
    const float* out_W      = (const float*)d_in[11];
    const float* out_b      = (const float*)d_in[12];
    const float* ln1_g      = (const float*)d_in[13];
    const float* ln1_b      = (const float*)d_in[14];
    const float* ffn_W1     = (const float*)d_in[15];
    const float* ffn_b1     = (const float*)d_in[16];
    const float* ffn_W2     = (const float*)d_in[17];
    const float* ffn_b2     = (const float*)d_in[18];
    const float* ln2_g      = (const float*)d_in[19];
    const float* ln2_b      = (const float*)d_in[20];

    float *px, *pqkv, *po, *ph, *py;
    cudaGetSymbolAddress((void**)&px,   g_x);
    cudaGetSymbolAddress((void**)&pqkv, g_qkv);
    cudaGetSymbolAddress((void**)&po,   g_o);
    cudaGetSymbolAddress((void**)&ph,   g_h);
    cudaGetSymbolAddress((void**)&py,   g_y);

    embed_kernel<<<TT, 256>>>(card_ids, action_ids, bet, card_tab, action_tab,
                              bet_W, bet_b, in_W, in_b);

    for (int i = 0; i < NLAYER; i++) {
        const float* qkvW_i = qkv_W  + (size_t)i * DD * D3;
        const float* qkvb_i = qkv_b  + (size_t)i * D3;
        const float* outW_i = out_W  + (size_t)i * DD * DD;
        const float* outb_i = out_b  + (size_t)i * DD;
        const float* l1g_i  = ln1_g  + (size_t)i * DD;
        const float* l1b_i  = ln1_b  + (size_t)i * DD;
        const float* w1_i   = ffn_W1 + (size_t)i * DD * FF;
        const float* b1_i   = ffn_b1 + (size_t)i * FF;
        const float* w2_i   = ffn_W2 + (size_t)i * FF * DD;
        const float* b2_i   = ffn_b2 + (size_t)i * DD;
        const float* l2g_i  = ln2_g  + (size_t)i * DD;
        const float* l2b_i  = ln2_b  + (size_t)i * DD;

        // qkv = x @ qkv_W + qkv_b
        sgemm_kernel<<<dim3(D3 / 64, TT / 64), 256>>>(px, qkvW_i, qkvb_i, pqkv, TT, D3, DD, 0);
        // scores + softmax + attn@V
        scores_kernel<<<dim3(16, 16, 32), 256>>>();
        softmax_kernel<<<dim3(LL, 32), 256>>>();
        attnv_kernel<<<dim3(16, 32), 256>>>();
        // attn out projection
        sgemm_kernel<<<dim3(DD / 64, TT / 64), 256>>>(po, outW_i, outb_i, py, TT, DD, DD, 0);
        // x = LN(x + attn)
        ln_kernel<<<TT, 256>>>(px, py, l1g_i, l1b_i, px);
        // ffn
        sgemm_kernel<<<dim3(FF / 64, TT / 64), 256>>>(px, w1_i, b1_i, ph, TT, FF, DD, 1);
        sgemm_kernel<<<dim3(DD / 64, TT / 64), 256>>>(ph, w2_i, b2_i, py, TT, DD, FF, 0);
        // x = LN(x + ffn)
        ln_kernel<<<TT, 256>>>(px, py, l2g_i, l2b_i, px);
    }

    final_kernel<<<dim3(BB, DD / 256), 256>>>((float*)d_out);
}

// round 3
// speedup vs baseline: 2.3288x; 2.3288x over previous
#include <cuda_runtime.h>
#include <cuda_bf16.h>
#include <cstdint>
#include <math.h>

// Problem constants
#define BB  2
#define LL  1024
#define DD  1024
#define NLAYER 8
#define FF  4096
#define TT  2048          // B*L
#define D3  3072          // 3*D

// ---------------- scratch (static device globals; no allocation) ----------------
__device__ float g_x   [TT * DD];
__device__ float g_qkv [TT * D3];
__device__ float g_att [(size_t)32 * 1024 * 1024];
__device__ float g_o   [TT * DD];
__device__ float g_h   [TT * FF];
__device__ float g_y   [TT * DD];
__device__ __align__(256) __nv_bfloat16 g_ah[(size_t)TT * FF];   // A hi plane (max 2048x4096)
__device__ __align__(256) __nv_bfloat16 g_al[(size_t)TT * FF];   // A lo plane
__device__ __align__(256) __nv_bfloat16 g_bh[(size_t)FF * DD];   // Bt hi plane (max 4096x1024)
__device__ __align__(256) __nv_bfloat16 g_bl[(size_t)FF * DD];   // Bt lo plane

// ============================ common PTX helpers ============================
__device__ __forceinline__ uint32_t smem_u32(const void* p) {
    uint32_t a;
    asm("{ .reg .u64 t; cvta.to.shared.u64 t, %1; cvt.u32.u64 %0, t; }" : "=r"(a) : "l"(p));
    return a;
}
__device__ __forceinline__ void cp16(uint32_t dst, const void* src) {
    asm volatile("cp.async.cg.shared.global [%0], [%1], 16;" :: "r"(dst), "l"(src));
}
__device__ __forceinline__ void cp_commit() { asm volatile("cp.async.commit_group;" ::: "memory"); }
__device__ __forceinline__ void cp_wait0()  { asm volatile("cp.async.wait_group 0;" ::: "memory"); }
__device__ __forceinline__ void cp_wait1()  { asm volatile("cp.async.wait_group 1;" ::: "memory"); }

__device__ __forceinline__ void ldx4(uint32_t& r0, uint32_t& r1, uint32_t& r2, uint32_t& r3, uint32_t addr) {
    asm volatile("ldmatrix.sync.aligned.m8n8.x4.shared.b16 {%0,%1,%2,%3}, [%4];"
                 : "=r"(r0), "=r"(r1), "=r"(r2), "=r"(r3) : "r"(addr));
}
__device__ __forceinline__ void mma_bf16(float* c, const uint32_t* a, uint32_t b0, uint32_t b1) {
    asm volatile("mma.sync.aligned.m16n8k16.row.col.f32.bf16.bf16.f32 "
                 "{%0,%1,%2,%3}, {%4,%5,%6,%7}, {%8,%9}, {%0,%1,%2,%3};"
                 : "+f"(c[0]), "+f"(c[1]), "+f"(c[2]), "+f"(c[3])
                 : "r"(a[0]), "r"(a[1]), "r"(a[2]), "r"(a[3]), "r"(b0), "r"(b1));
}

// ============================ tcgen05 helpers (sm_103a-only stage) ============================
#if defined(__CUDA_ARCH_FEAT_SM103_ALL)
__device__ __forceinline__ uint32_t elect_one() {
    uint32_t p;
    asm volatile("{\n\t.reg .pred p;\n\telect.sync _|p, 0xFFFFFFFF;\n\tselp.b32 %0, 1, 0, p;\n\t}" : "=r"(p));
    return p;
}
__device__ __forceinline__ void mbar_init(uint32_t a, uint32_t cnt) {
    asm volatile("mbarrier.init.shared.b64 [%0], %1;" :: "r"(a), "r"(cnt) : "memory");
}
__device__ __forceinline__ void mbar_inval(uint32_t a) {
    asm volatile("mbarrier.inval.shared.b64 [%0];" :: "r"(a) : "memory");
}
__device__ __forceinline__ void mbar_wait(uint32_t a, uint32_t parity) {
    uint32_t done;
    asm volatile("{\n\t.reg .pred p;\n\t"
                 "mbarrier.try_wait.parity.acquire.cta.shared::cta.b64 p, [%1], %2;\n\t"
                 "selp.b32 %0, 1, 0, p;\n\t}"
                 : "=r"(done) : "r"(a), "r"(parity) : "memory");
    if (!done) {
        asm volatile("{\n\t.reg .pred P1;\n\t"
                     "W_%=:\n\t"
                     "mbarrier.try_wait.parity.acquire.cta.shared::cta.b64 P1, [%0], %1, 0x989680;\n\t"
                     "@P1 bra.uni D_%=;\n\t"
                     "bra.uni W_%=;\n\t"
                     "D_%=:\n\t}"
                     :: "r"(a), "r"(parity) : "memory");
    }
}
__device__ __forceinline__ void fence_async() { asm volatile("fence.proxy.async.shared::cta;" ::: "memory"); }
__device__ __forceinline__ void tm_alloc(uint32_t smem_slot, uint32_t ncols) {
    asm volatile("tcgen05.alloc.cta_group::1.sync.aligned.shared::cta.b32 [%0], %1;"
                 :: "r"(smem_slot), "r"(ncols) : "memory");
}
__device__ __forceinline__ void tm_dealloc(uint32_t tmem, uint32_t ncols) {
    asm volatile("tcgen05.dealloc.cta_group::1.sync.aligned.b32 %0, %1;" :: "r"(tmem), "r"(ncols));
}
__device__ __forceinline__ void tm_relinq() {
    asm volatile("tcgen05.relinquish_alloc_permit.cta_group::1.sync.aligned;");
}
__device__ __forceinline__ void tm_commit(uint32_t mbar) {
    asm volatile("tcgen05.commit.cta_group::1.mbarrier::arrive::one.shared::cluster.b64 [%0];"
                 :: "r"(mbar) : "memory");
}
__device__ __forceinline__ void tm_fence_after() {
    asm volatile("tcgen05.fence::after_thread_sync;" ::: "memory");
}
__device__ __forceinline__ void tm_wait_ld() {
    asm volatile("tcgen05.wait::ld.sync.aligned;" ::: "memory");
}
__device__ __forceinline__ void mma_f16_ss(uint32_t d, uint64_t a, uint64_t b, uint32_t idesc, uint32_t en) {
    asm volatile("{\n\t.reg .pred p;\n\tsetp.ne.u32 p, %5, 0;\n\t"
                 "tcgen05.mma.cta_group::1.kind::f16 [%0], %1, %2, %3, {%4, %4, %4, %4}, p;\n\t}"
                 :: "r"(d), "l"(a), "l"(b), "r"(idesc), "r"(0u), "r"(en) : "memory");
}
__device__ __forceinline__ void ldtm32(uint32_t* r, uint32_t tmem) {
    asm volatile("tcgen05.ld.sync.aligned.32x32b.x32.b32 "
        "{%0, %1, %2, %3, %4, %5, %6, %7, %8, %9, %10, %11, %12, %13, %14, %15, "
        " %16, %17, %18, %19, %20, %21, %22, %23, %24, %25, %26, %27, %28, %29, %30, %31}, [%32];"
        : "=r"(r[0]),  "=r"(r[1]),  "=r"(r[2]),  "=r"(r[3]),  "=r"(r[4]),  "=r"(r[5]),  "=r"(r[6]),  "=r"(r[7]),
          "=r"(r[8]),  "=r"(r[9]),  "=r"(r[10]), "=r"(r[11]), "=r"(r[12]), "=r"(r[13]), "=r"(r[14]), "=r"(r[15]),
          "=r"(r[16]), "=r"(r[17]), "=r"(r[18]), "=r"(r[19]), "=r"(r[20]), "=r"(r[21]), "=r"(r[22]), "=r"(r[23]),
          "=r"(r[24]), "=r"(r[25]), "=r"(r[26]), "=r"(r[27]), "=r"(r[28]), "=r"(r[29]), "=r"(r[30]), "=r"(r[31])
        : "r"(tmem));
}
__device__ __forceinline__ uint32_t swz(uint32_t x) { return x ^ ((x >> 3) & 0x70); }
__device__ __forceinline__ uint64_t mk_desc(uint32_t addr) {
    return ((uint64_t)2 << 61) | ((uint64_t)1 << 46) | ((uint64_t)64 << 32) | ((uint64_t)1 << 16)
         | ((uint64_t)(addr >> 4) & 0x3FFF);
}
#endif

// ============================ tensor GEMM ============================
// C[M,N](fp32) = Ah@Bh^T + Al@Bh^T + Ah@Bl^T + bias (optional relu)
// A planes: [M][K] bf16 row-major. B planes: Bt[N][K] bf16 (K contiguous).
// Tile 128x128 in BOTH paths so grid is path-agnostic.
#define SMEM_REQ 132096

// mma.sync path constants
#define MP_STR   40                      // bf16 per smem row (32 data + 8 pad)
#define MP_ROWB  (MP_STR * 2)            // 80 bytes
#define MP_TILE  (128 * MP_ROWB)         // 10240 bytes per array
#define MP_BUF   (4 * MP_TILE)           // Ah,Al,Bh,Bl

__global__ void __launch_bounds__(256, 1) tgemm_kernel(
    const __nv_bfloat16* __restrict__ Ah,
    const __nv_bfloat16* __restrict__ Al,
    const __nv_bfloat16* __restrict__ Bh,
    const __nv_bfloat16* __restrict__ Bl,
    const float* __restrict__ bias,
    float* __restrict__ C,
    int M, int N, int K, int relu)
{
#if defined(__CUDA_ARCH_FEAT_SM103_ALL)
    // ---------------- tcgen05 path (only if an sm_103a stage exists) ----------------
    extern __shared__ char smem[];
    uint32_t sb = smem_u32(smem);
    int tid = threadIdx.x;
    int wid = tid >> 5, lane = tid & 31;

    if (wid == 0) tm_alloc(sb + 0, 128);
    __syncthreads();
    uint32_t tmem;
    asm volatile("ld.shared.b32 %0, [%1];" : "=r"(tmem) : "r"(sb + 0));
    if (tid == 0) { mbar_init(sb + 16, 1); mbar_init(sb + 24, 1); }
    __syncthreads();

    const int rowBase = blockIdx.y * 128;
    const int colBase = blockIdx.x * 128;
    const uint32_t mBar[2] = { sb + 16, sb + 24 };
    int phase[2] = { 0, 0 };
    const int nkb = K / 64;
    const int row = tid & 127;
    const int half = tid >> 7;           // 0/1 -> chunks 0-3 / 4-7

    for (int kb = 0; kb < nkb; kb++) {
        int buf = kb & 1;
        if (kb >= 2) { mbar_wait(mBar[buf], phase[buf]); phase[buf] ^= 1; }
        uint32_t bb = sb + 1024 + buf * 65536;
        const __nv_bfloat16* srcs[4] = {
            Ah + (size_t)(rowBase + row) * K + kb * 64,
            Al + (size_t)(rowBase + row) * K + kb * 64,
            Bh + (size_t)(colBase + row) * K + kb * 64,
            Bl + (size_t)(colBase + row) * K + kb * 64 };
        #pragma unroll
        for (int a = 0; a < 4; a++) {
            #pragma unroll
            for (int j = 0; j < 4; j++) {
                int chunk = half * 4 + j;
                cp16(bb + a * 16384 + swz(row * 128 + chunk * 16), srcs[a] + chunk * 8);
            }
        }
        cp_commit();
        cp_wait0();
        __syncthreads();

        if (wid == 0) {
            if (elect_one()) {
                fence_async();
                uint64_t ahd = mk_desc(bb);
                uint64_t ald = mk_desc(bb + 16384);
                uint64_t bhd = mk_desc(bb + 32768);
                uint64_t bld = mk_desc(bb + 49152);
                #pragma unroll
                for (int s = 0; s < 4; s++) {
                    mma_f16_ss(tmem, ahd + s * 2, bhd + s * 2, 0x8200490u, (kb > 0 || s > 0) ? 1u : 0u);
                    mma_f16_ss(tmem, ald + s * 2, bhd + s * 2, 0x8200490u, 1u);
                    mma_f16_ss(tmem, ahd + s * 2, bld + s * 2, 0x8200490u, 1u);
                }
                tm_commit(mBar[buf]);
            }
        }
    }

    int lastBuf = (nkb - 1) & 1;
    __syncthreads();
    mbar_wait(mBar[lastBuf], phase[lastBuf]);
    tm_fence_after();

    {
        int colHalf = (wid >> 2) * 64;
        int m = rowBase + (wid & 3) * 32 + lane;
        float* Crow = C + (size_t)m * N;
        #pragma unroll
        for (int c0 = 0; c0 < 64; c0 += 32) {
            uint32_t d[32];
            ldtm32(d, tmem + colHalf + c0);
            tm_wait_ld();
            int n0 = colBase + colHalf + c0;
            #pragma unroll
            for (int j = 0; j < 32; j += 4) {
                float4 o;
                o.x = __uint_as_float(d[j + 0]) + bias[n0 + j + 0];
                o.y = __uint_as_float(d[j + 1]) + bias[n0 + j + 1];
                o.z = __uint_as_float(d[j + 2]) + bias[n0 + j + 2];
                o.w = __uint_as_float(d[j + 3]) + bias[n0 + j + 3];
                if (relu) {
                    o.x = fmaxf(o.x, 0.f); o.y = fmaxf(o.y, 0.f);
                    o.z = fmaxf(o.z, 0.f); o.w = fmaxf(o.w, 0.f);
                }
                *(float4*)(Crow + n0 + j) = o;
            }
        }
    }

    __syncthreads();
    if (tid == 0) { mbar_inval(sb + 16); mbar_inval(sb + 24); }
    __syncthreads();
    if (wid == 0) { tm_relinq(); tm_dealloc(tmem, 128); }

#else
    // ---------------- mma.sync fallback path (compute_103 baseline) ----------------
    extern __shared__ char smem[];
    uint32_t sb = smem_u32(smem);
    int tid = threadIdx.x;
    int wid = tid >> 5, lane = tid & 31;
    int wm = (wid & 1) * 64;             // warp m offset in tile
    int wn = (wid >> 1) * 32;            // warp n offset in tile
    const int rowBase = blockIdx.y * 128;
    const int colBase = blockIdx.x * 128;
    const int nkb = K / 32;

    float acc[4][4][4];
    #pragma unroll
    for (int i = 0; i < 4; i++)
        #pragma unroll
        for (int j = 0; j < 4; j++)
            #pragma unroll
            for (int r = 0; r < 4; r++) acc[i][j][r] = 0.f;

    // loader: thread -> row = tid>>1 (0..127), c = (tid&1)*16 elems
    const int lrow = tid >> 1;
    const int lc = (tid & 1) * 16;

    auto loadTile = [&](int kb, int buf) {
        uint32_t db = sb + buf * MP_BUF;
        uint32_t doff = lrow * MP_ROWB + lc * 2;
        const __nv_bfloat16* pAh = Ah + (size_t)(rowBase + lrow) * K + kb * 32 + lc;
        const __nv_bfloat16* pAl = Al + (size_t)(rowBase + lrow) * K + kb * 32 + lc;
        const __nv_bfloat16* pBh = Bh + (size_t)(colBase + lrow) * K + kb * 32 + lc;
        const __nv_bfloat16* pBl = Bl + (size_t)(colBase + lrow) * K + kb * 32 + lc;
        cp16(db + 0 * MP_TILE + doff,      pAh);     cp16(db + 0 * MP_TILE + doff + 16, pAh + 8);
        cp16(db + 1 * MP_TILE + doff,      pAl);     cp16(db + 1 * MP_TILE + doff + 16, pAl + 8);
        cp16(db + 2 * MP_TILE + doff,      pBh);     cp16(db + 2 * MP_TILE + doff + 16, pBh + 8);
        cp16(db + 3 * MP_TILE + doff,      pBl);     cp16(db + 3 * MP_TILE + doff + 16, pBl + 8);
    };

    loadTile(0, 0);
    cp_commit();

    for (int kb = 0; kb < nkb; kb++) {
        int buf = kb & 1;
        if (kb + 1 < nkb) { loadTile(kb + 1, buf ^ 1); cp_commit(); cp_wait1(); }
        else              { cp_wait0(); }
        __syncthreads();

        uint32_t ab = sb + buf * MP_BUF;
        uint32_t lb = ab + MP_TILE;
        uint32_t hb = ab + 2 * MP_TILE;
        uint32_t ob = ab + 3 * MP_TILE;

        #pragma unroll
        for (int kk = 0; kk < 2; kk++) {
            int k0 = kk * 16;
            // A fragment addresses: row = wm + mi*16 + (lane&15); col = k0 + (lane>>4)*8
            uint32_t aoff = (uint32_t)(wm + (lane & 15)) * MP_ROWB + (k0 + (lane >> 4) * 8) * 2;
            uint32_t ah[4][4], al[4][4];
            #pragma unroll
            for (int mi = 0; mi < 4; mi++) {
                ldx4(ah[mi][0], ah[mi][1], ah[mi][2], ah[mi][3], ab + aoff + mi * 16 * MP_ROWB);
                ldx4(al[mi][0], al[mi][1], al[mi][2], al[mi][3], lb + aoff + mi * 16 * MP_ROWB);
            }
            // B fragments: row = wn + (lane>>4)*8 + (lane&7); col = k0 + ((lane>>3)&1)*8
            uint32_t boff = (uint32_t)(wn + ((lane >> 4) * 8) + (lane & 7)) * MP_ROWB
                          + (k0 + ((lane >> 3) & 1) * 8) * 2;
            uint32_t bh[8], bl[8];
            ldx4(bh[0], bh[1], bh[2], bh[3], hb + boff);
            ldx4(bh[4], bh[5], bh[6], bh[7], hb + boff + 16 * MP_ROWB);
            ldx4(bl[0], bl[1], bl[2], bl[3], ob + boff);
            ldx4(bl[4], bl[5], bl[6], bl[7], ob + boff + 16 * MP_ROWB);

            #pragma unroll
            for (int mi = 0; mi < 4; mi++)
                #pragma unroll
                for (int ni = 0; ni < 4; ni++) {
                    mma_bf16(acc[mi][ni], ah[mi], bh[2 * ni], bh[2 * ni + 1]);
                    mma_bf16(acc[mi][ni], al[mi], bh[2 * ni], bh[2 * ni + 1]);
                    mma_bf16(acc[mi][ni], ah[mi], bl[2 * ni], bl[2 * ni + 1]);
                }
        }
        __syncthreads();
    }

    // epilogue
    int g = lane >> 2, t = lane & 3;
    #pragma unroll
    for (int mi = 0; mi < 4; mi++) {
        #pragma unroll
        for (int ni = 0; ni < 4; ni++) {
            int m = rowBase + wm + mi * 16 + g;
            int n = colBase + wn + ni * 8 + 2 * t;
            float b0 = bias[n], b1 = bias[n + 1];
            float2 v0, v1;
            v0.x = acc[mi][ni][0] + b0; v0.y = acc[mi][ni][1] + b1;
            v1.x = acc[mi][ni][2] + b0; v1.y = acc[mi][ni][3] + b1;
            if (relu) {
                v0.x = fmaxf(v0.x, 0.f); v0.y = fmaxf(v0.y, 0.f);
                v1.x = fmaxf(v1.x, 0.f); v1.y = fmaxf(v1.y, 0.f);
            }
            *(float2*)&C[(size_t)m * N + n] = v0;
            *(float2*)&C[(size_t)(m + 8) * N + n] = v1;
        }
    }
#endif
}

// ============================ split/convert kernels ============================
__global__ void splitA_kernel(const float* __restrict__ X,
                              __nv_bfloat16* __restrict__ Ahp,
                              __nv_bfloat16* __restrict__ Alp)
{
    size_t idx = (size_t)blockIdx.x * 256 + threadIdx.x;
    float x = X[idx];
    __nv_bfloat16 h = __float2bfloat16(x);
    __nv_bfloat16 l = __float2bfloat16(x - __bfloat162float(h));
    Ahp[idx] = h;
    Alp[idx] = l;
}

// W[K,N] fp32 -> Bth[N][K], Btl[N][K] bf16 (transposed)
__global__ void convW_kernel(const float* __restrict__ W,
                             __nv_bfloat16* __restrict__ Bth,
                             __nv_bfloat16* __restrict__ Btl,
                             int K, int N)
{
    __shared__ float tile[32][33];
    int tid = threadIdx.x;
    int tx = tid & 31, ty = tid >> 5;
    int kb = blockIdx.y * 32, nb = blockIdx.x * 32;
    #pragma unroll
    for (int r = 0; r < 4; r++)
        tile[ty + 8 * r][tx] = W[(size_t)(kb + ty + 8 * r) * N + nb + tx];
    __syncthreads();
    #pragma unroll
    for (int r = 0; r < 4; r++) {
        int n = nb + ty + 8 * r;
        int k = kb + tx;
        float w = tile[tx][ty + 8 * r];
        __nv_bfloat16 h = __float2bfloat16(w);
        __nv_bfloat16 l = __float2bfloat16(w - __bfloat162float(h));
        Bth[(size_t)n * K + k] = h;
        Btl[(size_t)n * K + k] = l;
    }
}

// ---------------- embedding + input proj + posenc ----------------
__global__ void embed_kernel(const int* __restrict__ card_ids,
                             const int* __restrict__ action_ids,
                             const float* __restrict__ bet,
                             const float* __restrict__ card_tab,
                             const float* __restrict__ action_tab,
                             const float* __restrict__ bet_W,
                             const float* __restrict__ bet_b,
                             const float* __restrict__ in_W,
                             const float* __restrict__ in_b)
{
    int t = blockIdx.x;
    int l = t & (LL - 1);
    __shared__ float tok[48];
    int tid = threadIdx.x;
    if (tid < 16)       tok[tid] = card_tab[card_ids[t] * 16 + tid];
    else if (tid < 32)  tok[tid] = action_tab[action_ids[t] * 16 + (tid - 16)];
    else if (tid < 48)  tok[tid] = bet[t] * bet_W[tid - 32] + bet_b[tid - 32];
    __syncthreads();

    const float cdiv = -9.210340371976184f / 1024.0f;
    for (int d = tid; d < DD; d += 256) {
        float acc = in_b[d];
        #pragma unroll
        for (int c = 0; c < 48; c++) acc += tok[c] * in_W[c * DD + d];
        int j2 = d & ~1;
        float ang = (float)l * expf((float)j2 * cdiv);
        float pe = (d & 1) ? cosf(ang) : sinf(ang);
        g_x[t * DD + d] = acc + pe;
    }
}

// ---------------- attention scores (fp32) ----------------
__global__ void __launch_bounds__(256) scores_kernel()
{
    int kt = blockIdx.x, qt = blockIdx.y, bh = blockIdx.z;
    if (kt > qt) return;
    int b = bh >> 4, h = bh & 15;
    __shared__ float Qs[64][65];
    __shared__ float Ks[64][65];
    int tid = threadIdx.x;

    for (int i = tid; i < 4096; i += 256) {
        int r = i >> 6, dd = i & 63;
        Qs[dd][r] = g_qkv[(size_t)(b * LL + qt * 64 + r) * D3 + h * 64 + dd];
        Ks[dd][r] = g_qkv[(size_t)(b * LL + kt * 64 + r) * D3 + DD + h * 64 + dd];
    }
    __syncthreads();

    int tx = tid & 15, ty = tid >> 4;
    float acc[4][4] = {};
    #pragma unroll 8
    for (int dd = 0; dd < 64; dd++) {
        float a[4], bv[4];
        #pragma unroll
        for (int i = 0; i < 4; i++) a[i] = Qs[dd][ty * 4 + i];
        #pragma unroll
        for (int j = 0; j < 4; j++) bv[j] = Ks[dd][tx * 4 + j];
        #pragma unroll
        for (int i = 0; i < 4; i++)
            #pragma unroll
            for (int j = 0; j < 4; j++)
                acc[i][j] += a[i] * bv[j];
    }

    #pragma unroll
    for (int i = 0; i < 4; i++) {
        int q = qt * 64 + ty * 4 + i;
        #pragma unroll
        for (int j = 0; j < 4; j++) {
            int k = kt * 64 + tx * 4 + j;
            g_att[((size_t)bh * LL + q) * LL + k] = (k <= q) ? acc[i][j] * 0.125f : -1e30f;
        }
    }
}

// ---------------- row softmax ----------------
__global__ void __launch_bounds__(256) softmax_kernel()
{
    int q = blockIdx.x, bh = blockIdx.y;
    int n = ((q >> 6) + 1) << 6;
    float* row = g_att + ((size_t)bh * LL + q) * LL;
    int tid = threadIdx.x, lane = tid & 31, warp = tid >> 5;
    __shared__ float redm[8];
    __shared__ float reds[8];

    float v[4];
    float mx = -1e30f;
    #pragma unroll
    for (int r = 0; r < 4; r++) {
        int k = tid + r * 256;
        v[r] = (k < n) ? row[k] : -1e30f;
        mx = fmaxf(mx, v[r]);
    }
    #pragma unroll
    for (int o = 16; o > 0; o >>= 1) mx = fmaxf(mx, __shfl_xor_sync(0xffffffffu, mx, o));
    if (lane == 0) redm[warp] = mx;
    __syncthreads();
    if (tid == 0) {
        float m = redm[0];
        #pragma unroll
        for (int i = 1; i < 8; i++) m = fmaxf(m, redm[i]);
        redm[0] = m;
    }
    __syncthreads();
    mx = redm[0];

    float s = 0.f;
    #pragma unroll
    for (int r = 0; r < 4; r++) {
        int k = tid + r * 256;
        if (k < n) { v[r] = expf(v[r] - mx); s += v[r]; }
        else v[r] = 0.f;
    }
    #pragma unroll
    for (int o = 16; o > 0; o >>= 1) s += __shfl_xor_sync(0xffffffffu, s, o);
    if (lane == 0) reds[warp] = s;
    __syncthreads();
    if (tid == 0) {
        float t = 0.f;
        #pragma unroll
        for (int i = 0; i < 8; i++) t += reds[i];
        reds[0] = t;
    }
    __syncthreads();
    float inv = 1.f / reds[0];

    #pragma unroll
    for (int r = 0; r < 4; r++) {
        int k = tid + r * 256;
        if (k < n) row[k] = v[r] * inv;
    }
}

// ---------------- O = attn @ V (fp32) ----------------
__global__ void __launch_bounds__(256) attnv_kernel()
{
    int qt = blockIdx.x, bh = blockIdx.y;
    int b = bh >> 4, h = bh & 15;
    __shared__ float At[64][65];
    __shared__ float Vs[64][64];
    int tid = threadIdx.x, tx = tid & 15, ty = tid >> 4;
    float acc[4][4] = {};

    for (int kt = 0; kt <= qt; kt++) {
        for (int i = tid; i < 4096; i += 256) {
            int r = i >> 6, c = i & 63;
            At[c][r] = g_att[((size_t)bh * LL + qt * 64 + r) * LL + kt * 64 + c];
            Vs[r][c] = g_qkv[(size_t)(b * LL + kt * 64 + r) * D3 + 2 * DD + h * 64 + c];
        }
        __syncthreads();
        #pragma unroll 8
        for (int kk = 0; kk < 64; kk++) {
            float a[4];
            #pragma unroll
            for (int i = 0; i < 4; i++) a[i] = At[kk][ty * 4 + i];
            float4 bv = *(const float4*)&Vs[kk][tx * 4];
            acc[0][0] += a[0] * bv.x; acc[0][1] += a[0] * bv.y; acc[0][2] += a[0] * bv.z; acc[0][3] += a[0] * bv.w;
            acc[1][0] += a[1] * bv.x; acc[1][1] += a[1] * bv.y; acc[1][2] += a[1] * bv.z; acc[1][3] += a[1] * bv.w;
            acc[2][0] += a[2] * bv.x; acc[2][1] += a[2] * bv.y; acc[2][2] += a[2] * bv.z; acc[2][3] += a[2] * bv.w;
            acc[3][0] += a[3] * bv.x; acc[3][1] += a[3] * bv.y; acc[3][2] += a[3] * bv.z; acc[3][3] += a[3] * bv.w;
        }
        __syncthreads();
    }

    #pragma unroll
    for (int i = 0; i < 4; i++) {
        int q = qt * 64 + ty * 4 + i;
        #pragma unroll
        for (int j = 0; j < 4; j++)
            g_o[(size_t)(b * LL + q) * DD + h * 64 + tx * 4 + j] = acc[i][j];
    }
}

// ---------------- residual add + layernorm ----------------
__global__ void __launch_bounds__(256) ln_kernel(const float* __restrict__ xin,
                                                 const float* __restrict__ delta,
                                                 const float* __restrict__ gamma,
                                                 const float* __restrict__ beta,
                                                 float* __restrict__ out)
{
    int row = blockIdx.x, tid = threadIdx.x, lane = tid & 31, warp = tid >> 5;
    __shared__ float red1[8];
    __shared__ float red2[8];
    __shared__ float stats[2];

    float v[4];
    float s = 0.f, s2 = 0.f;
    #pragma unroll
    for (int r = 0; r < 4; r++) {
        int d = tid + r * 256;
        float x = xin[(size_t)row * DD + d] + delta[(size_t)row * DD + d];
        v[r] = x; s += x; s2 += x * x;
    }
    #pragma unroll
    for (int o = 16; o > 0; o >>= 1) {
        s  += __shfl_xor_sync(0xffffffffu, s, o);
        s2 += __shfl_xor_sync(0xffffffffu, s2, o);
    }
    if (lane == 0) { red1[warp] = s; red2[warp] = s2; }
    __syncthreads();
    if (tid == 0) {
        float a = 0.f, c = 0.f;
        #pragma unroll
        for (int i = 0; i < 8; i++) { a += red1[i]; c += red2[i]; }
        float mu = a * (1.0f / DD);
        float var = c * (1.0f / DD) - mu * mu;
        stats[0] = mu;
        stats[1] = rsqrtf(var + 1e-5f);
    }
    __syncthreads();
    float mu = stats[0], rstd = stats[1];
    #pragma unroll
    for (int r = 0; r < 4; r++) {
        int d = tid + r * 256;
        out[(size_t)row * DD + d] = (v[r] - mu) * rstd * gamma[d] + beta[d];
    }
}

// ---------------- extract x[:, -1] ----------------
__global__ void final_kernel(float* __restrict__ out)
{
    int b = blockIdx.x;
    int d = blockIdx.y * 256 + threadIdx.x;
    out[b * DD + d] = g_x[(size_t)(b * LL + (LL - 1)) * DD + d];
}

// ---------------- host launch ----------------
extern "C" void kernel_launch(void* const* d_in, const int* in_sizes, int n_in,
                              void* d_out, int out_size)
{
    const int*   card_ids   = (const int*)  d_in[0];
    const int*   action_ids = (const int*)  d_in[1];
    const float* bet        = (const float*)d_in[2];
    const float* card_tab   = (const float*)d_in[3];
    const float* action_tab = (const float*)d_in[4];
    const float* bet_W      = (const float*)d_in[5];
    const float* bet_b      = (const float*)d_in[6];
    const float* in_W       = (const float*)d_in[7];
    const float* in_b       = (const float*)d_in[8];
    const float* qkv_W      = (const float*)d_in[9];
    const float* qkv_b      = (const float*)d_in[10];
    const float* out_W      = (const float*)d_in[11];
    const float* out_b      = (const float*)d_in[12];
    const float* ln1_g      = (const float*)d_in[13];
    const float* ln1_b      = (const float*)d_in[14];
    const float* ffn_W1     = (const float*)d_in[15];
    const float* ffn_b1     = (const float*)d_in[16];
    const float* ffn_W2     = (const float*)d_in[17];
    const float* ffn_b2     = (const float*)d_in[18];
    const float* ln2_g      = (const float*)d_in[19];
    const float* ln2_b      = (const float*)d_in[20];

    float *px, *pqkv, *po, *ph, *py;
    __nv_bfloat16 *pah, *pal, *pbh, *pbl;
    cudaGetSymbolAddress((void**)&px,   g_x);
    cudaGetSymbolAddress((void**)&pqkv, g_qkv);
    cudaGetSymbolAddress((void**)&po,   g_o);
    cudaGetSymbolAddress((void**)&ph,   g_h);
    cudaGetSymbolAddress((void**)&py,   g_y);
    cudaGetSymbolAddress((void**)&pah,  g_ah);
    cudaGetSymbolAddress((void**)&pal,  g_al);
    cudaGetSymbolAddress((void**)&pbh,  g_bh);
    cudaGetSymbolAddress((void**)&pbl,  g_bl);

    static int configured = 0;
    if (!configured) {
        cudaFuncSetAttribute(tgemm_kernel, cudaFuncAttributeMaxDynamicSharedMemorySize, SMEM_REQ);
        configured = 1;
    }

    embed_kernel<<<TT, 256>>>(card_ids, action_ids, bet, card_tab, action_tab,
                              bet_W, bet_b, in_W, in_b);

    for (int i = 0; i < NLAYER; i++) {
        const float* qkvW_i = qkv_W  + (size_t)i * DD * D3;
        const float* qkvb_i = qkv_b  + (size_t)i * D3;
        const float* outW_i = out_W  + (size_t)i * DD * DD;
        const float* outb_i = out_b  + (size_t)i * DD;
        const float* l1g_i  = ln1_g  + (size_t)i * DD;
        const float* l1b_i  = ln1_b  + (size_t)i * DD;
        const float* w1_i   = ffn_W1 + (size_t)i * DD * FF;
        const float* b1_i   = ffn_b1 + (size_t)i * FF;
        const float* w2_i   = ffn_W2 + (size_t)i * FF * DD;
        const float* b2_i   = ffn_b2 + (size_t)i * DD;
        const float* l2g_i  = ln2_g  + (size_t)i * DD;
        const float* l2b_i  = ln2_b  + (size_t)i * DD;

        // qkv = x @ qkv_W + b  (K=1024, N=3072)
        splitA_kernel<<<TT * DD / 256, 256>>>(px, pah, pal);
        convW_kernel<<<dim3(D3 / 32, DD / 32), 256>>>(qkvW_i, pbh, pbl, DD, D3);
        tgemm_kernel<<<dim3(D3 / 128, TT / 128), 256, SMEM_REQ>>>(pah, pal, pbh, pbl, qkvb_i, pqkv, TT, D3, DD, 0);

        // attention (fp32)
        scores_kernel<<<dim3(16, 16, 32), 256>>>();
        softmax_kernel<<<dim3(LL, 32), 256>>>();
        attnv_kernel<<<dim3(16, 32), 256>>>();

        // attn out projection (K=1024, N=1024)
        splitA_kernel<<<TT * DD / 256, 256>>>(po, pah, pal);
        convW_kernel<<<dim3(DD / 32, DD / 32), 256>>>(outW_i, pbh, pbl, DD, DD);
        tgemm_kernel<<<dim3(DD / 128, TT / 128), 256, SMEM_REQ>>>(pah, pal, pbh, pbl, outb_i, py, TT, DD, DD, 0);

        ln_kernel<<<TT, 256>>>(px, py, l1g_i, l1b_i, px);

        // ffn1 (K=1024, N=4096, relu)
        splitA_kernel<<<TT * DD / 256, 256>>>(px, pah, pal);
        convW_kernel<<<dim3(FF / 32, DD / 32), 256>>>(w1_i, pbh, pbl, DD, FF);
        tgemm_kernel<<<dim3(FF / 128, TT / 128), 256, SMEM_REQ>>>(pah, pal, pbh, pbl, b1_i, ph, TT, FF, DD, 1);

        // ffn2 (K=4096, N=1024)
        splitA_kernel<<<TT * FF / 256, 256>>>(ph, pah, pal);
        convW_kernel<<<dim3(DD / 32, FF / 32), 256>>>(w2_i, pbh, pbl, FF, DD);
        tgemm_kernel<<<dim3(DD / 128, TT / 128), 256, SMEM_REQ>>>(pah, pal, pbh, pbl, b2_i, py, TT, DD, FF, 0);

        ln_kernel<<<TT, 256>>>(px, py, l2g_i, l2b_i, px);
    }

    final_kernel<<<dim3(BB, DD / 256), 256>>>((float*)d_out);
}